// round 14
// baseline (speedup 1.0000x reference)
#include <cuda_runtime.h>
#include <cuda_fp16.h>
#include <math.h>
#include <stdint.h>

// Problem dims
#define Bb 2
#define Tt 1024
#define Cc 2048
#define Hh 16
#define DK 128
#define SC 1024
#define SS 2048
#define KDIM 2048
#define NMAT 4194304ull   // 2048*2048

#define RSQRT_DK 0.08838834764831845f

// HMMA GEMM tiling: CTA tile 128(M) x 128(N) x 64(K), 256 threads,
// 8 warps 2(m) x 4(n), warp tile 64x32. 2-stage pipeline, BK=64.
#define MM_BK 64
#define MM_LDS_B 144                       // bytes per smem row (64 fp16 + 16 pad)
#define MM_MATA 18432                      // 128 rows * 144
#define MM_STAGE (2 * MM_MATA)             // 36864 (A + B)
#define MM_SMEM (2 * MM_STAGE)             // 73728
#define MM_KSTEPS (KDIM / MM_BK)           // 32

// Flash-attention tiling: m-tile 128, s-tile 64, d=128, 8 warps (16 rows each)
#define FA_LDQ 272
#define FA_LDK 272
#define FA_QBYTES (128 * FA_LDQ)           // 34816
#define FA_KBYTES (64 * FA_LDK)            // 17408
#define FA_KV_STAGE (2 * FA_KBYTES)        // 34816
#define FA_SMEM (FA_QBYTES + 2 * FA_KV_STAGE)  // 104448

// ---------------------------------------------------------------------------
// Scratch (device globals)
// ---------------------------------------------------------------------------
__device__ __half g_xh[NMAT];                             // x fp16
__device__ __half g_w4[4 * NMAT];                         // Wq,Wk,Wv,Wo fp16
__device__ __half g_kc[NMAT];                             // cache_k fp16
__device__ __half g_vc[NMAT];                             // cache_v fp16
__device__ __half g_qh[NMAT];                             // Q fp16 [bh,t,d] scaled
__device__ __half g_ah[NMAT];                             // attn fp16 [b,t,h,d]

// ---------------------------------------------------------------------------
// PTX helpers
// ---------------------------------------------------------------------------
__device__ __forceinline__ uint32_t smem_u32(const void* p) {
    uint32_t a;
    asm("{ .reg .u64 t; cvta.to.shared.u64 t, %1; cvt.u32.u64 %0, t; }" : "=r"(a) : "l"(p));
    return a;
}
#define CP_ASYNC16(saddr, gaddr) \
    asm volatile("cp.async.cg.shared.global [%0], [%1], 16;" :: "r"(saddr), "l"(gaddr))
#define CP_COMMIT() asm volatile("cp.async.commit_group;" ::: "memory")
#define CP_WAIT(n)  asm volatile("cp.async.wait_group %0;" :: "n"(n) : "memory")

__device__ __forceinline__ void ldm_x4(uint32_t addr, uint32_t* r) {
    asm volatile("ldmatrix.sync.aligned.m8n8.x4.shared.b16 {%0,%1,%2,%3}, [%4];"
        : "=r"(r[0]), "=r"(r[1]), "=r"(r[2]), "=r"(r[3]) : "r"(addr));
}
__device__ __forceinline__ void ldm_x2(uint32_t addr, uint32_t* r) {
    asm volatile("ldmatrix.sync.aligned.m8n8.x2.shared.b16 {%0,%1}, [%2];"
        : "=r"(r[0]), "=r"(r[1]) : "r"(addr));
}
__device__ __forceinline__ void ldm_x2_trans(uint32_t addr, uint32_t* r) {
    asm volatile("ldmatrix.sync.aligned.m8n8.x2.trans.shared.b16 {%0,%1}, [%2];"
        : "=r"(r[0]), "=r"(r[1]) : "r"(addr));
}
__device__ __forceinline__ void mma_f16(float* d, const uint32_t* a, const uint32_t* b) {
    asm volatile("mma.sync.aligned.m16n8k16.row.col.f32.f16.f16.f32 "
        "{%0,%1,%2,%3}, {%4,%5,%6,%7}, {%8,%9}, {%0,%1,%2,%3};"
        : "+f"(d[0]), "+f"(d[1]), "+f"(d[2]), "+f"(d[3])
        : "r"(a[0]), "r"(a[1]), "r"(a[2]), "r"(a[3]), "r"(b[0]), "r"(b[1]));
}
__device__ __forceinline__ uint32_t pack2h(float a, float b) {
    __half2 h = __floats2half2_rn(a, b);
    return *reinterpret_cast<uint32_t*>(&h);
}

// ---------------------------------------------------------------------------
// conversions (fused with cache copy)
// ---------------------------------------------------------------------------
__global__ void convert7_kernel(const float4* __restrict__ x,
                                const float4* __restrict__ wq,
                                const float4* __restrict__ wk,
                                const float4* __restrict__ wv,
                                const float4* __restrict__ wo,
                                const float4* __restrict__ ck,
                                const float4* __restrict__ cv,
                                float4* __restrict__ Kout,
                                float4* __restrict__ Vout) {
    int id = blockIdx.x * blockDim.x + threadIdx.x;
    const int per = (int)(NMAT / 4);
    int mat = id / per;
    int rem = id - mat * per;
    const float4* srcs[7] = {x, wq, wk, wv, wo, ck, cv};
    float4 v = srcs[mat][rem];
    __half* base;
    if (mat == 0)      base = g_xh;
    else if (mat <= 4) base = g_w4 + (size_t)(mat - 1) * NMAT;
    else if (mat == 5) base = g_kc;
    else               base = g_vc;
    __half2* d = reinterpret_cast<__half2*>(base) + rem * 2;
    d[0] = __halves2half2(__float2half(v.x), __float2half(v.y));
    d[1] = __halves2half2(__float2half(v.z), __float2half(v.w));
    if (mat >= 5) {
        int pos = rem & 31;
        int row = rem >> 5;
        int s = row & (SC - 1);
        int bh = row >> 10;
        int dst = (((bh * SS) + s) << 5) + pos;
        ((mat == 5) ? Kout : Vout)[dst] = v;
    }
}

// ---------------------------------------------------------------------------
// HMMA fp16 GEMM (256 threads, 8 warps 2x4, CTA 128x128, BK=64, 2-stage,
// one barrier per k-iter, load(i+1) overlapped with compute(i))
// ---------------------------------------------------------------------------
__global__ __launch_bounds__(256, 2)
void mm_hmma_kernel(int mode, float* __restrict__ Kout, float* __restrict__ Vout,
                    float* __restrict__ out) {
    extern __shared__ char sm[];
    const uint32_t sbu = smem_u32(sm);
    const int tid = threadIdx.x;
    const int wid = tid >> 5, lane = tid & 31;
    const int warp_m = wid >> 2;          // 0..1
    const int warp_n = wid & 3;           // 0..3

    const int proj = blockIdx.z;
    const __half *As, *Bs;
    if (mode == 0) {
        As = g_xh;
        Bs = g_w4 + (size_t)proj * NMAT;
    } else {
        As = g_ah;
        Bs = g_w4 + (size_t)3 * NMAT;
    }
    const int m0 = blockIdx.x * 128, n0 = blockIdx.y * 128;

    // cp.async: 2048 16B chunks per stage (A 1024, B 1024), 8 per thread
    const __half* gptr[8];
    uint32_t soff[8];
#pragma unroll
    for (int j = 0; j < 8; j++) {
        int c = j * 256 + tid;
        int idx = c & 1023;
        int r = idx >> 3, c8 = idx & 7;
        if (c < 1024) {
            gptr[j] = As + (size_t)(m0 + r) * KDIM + c8 * 8;
            soff[j] = (uint32_t)(r * MM_LDS_B + c8 * 16);
        } else {
            gptr[j] = Bs + (size_t)(n0 + r) * KDIM + c8 * 8;
            soff[j] = (uint32_t)(MM_MATA + r * MM_LDS_B + c8 * 16);
        }
    }

    const uint32_t a_row  = (uint32_t)(warp_m * 64 + (lane & 15));
    const uint32_t a_kb   = (uint32_t)(((lane >> 4) << 3) * 2);
    const uint32_t b_row4 = (uint32_t)(warp_n * 32 + (lane & 7) + ((lane >> 4) << 3));
    const uint32_t b_kb4  = (uint32_t)(((lane >> 3) & 1) << 4);

    float acc[4][4][4];
#pragma unroll
    for (int mi = 0; mi < 4; mi++)
#pragma unroll
        for (int ni = 0; ni < 4; ni++)
#pragma unroll
            for (int q = 0; q < 4; q++) acc[mi][ni][q] = 0.f;

    // prologue: stage 0
#pragma unroll
    for (int j = 0; j < 8; j++) CP_ASYNC16(sbu + soff[j], gptr[j]);
    CP_COMMIT();

    for (int i = 0; i < MM_KSTEPS; i++) {
        __syncthreads();   // all warps done computing stage (i-1) -> its buffer is free
        if (i + 1 < MM_KSTEPS) {
            const uint32_t sb2 = sbu + ((i + 1) & 1) * MM_STAGE;
            const int k0 = (i + 1) * MM_BK;
#pragma unroll
            for (int j = 0; j < 8; j++) CP_ASYNC16(sb2 + soff[j], gptr[j] + k0);
            CP_COMMIT();
            CP_WAIT(1);    // stage i complete; stage i+1 still in flight
        } else {
            CP_WAIT(0);
        }
        __syncthreads();   // make stage i visible to all warps

        const uint32_t stage = sbu + (i & 1) * MM_STAGE;
#pragma unroll
        for (int kk = 0; kk < 4; kk++) {
            const uint32_t kb = (uint32_t)(kk * 32);
            uint32_t a_f[4][4], b4[2][4];
#pragma unroll
            for (int nj = 0; nj < 2; nj++) {
                uint32_t baddr = stage + MM_MATA +
                                 (b_row4 + nj * 16) * MM_LDS_B + b_kb4 + kb;
                ldm_x4(baddr, b4[nj]);
            }
#pragma unroll
            for (int mi = 0; mi < 4; mi++) {
                uint32_t aaddr = stage + (a_row + mi * 16) * MM_LDS_B + a_kb + kb;
                ldm_x4(aaddr, a_f[mi]);
            }
#pragma unroll
            for (int mi = 0; mi < 4; mi++)
#pragma unroll
                for (int ni = 0; ni < 4; ni++)
                    mma_f16(acc[mi][ni], a_f[mi], &b4[ni >> 1][(ni & 1) * 2]);
        }
    }

    const int gid = lane >> 2, tc = lane & 3;
#pragma unroll
    for (int mi = 0; mi < 4; mi++) {
#pragma unroll
        for (int ni = 0; ni < 4; ni++) {
            int mrow0 = m0 + warp_m * 64 + mi * 16 + gid;
            int ncol  = n0 + warp_n * 32 + ni * 8 + tc * 2;
#pragma unroll
            for (int half = 0; half < 2; half++) {
                int m = mrow0 + half * 8;
                float v0 = acc[mi][ni][half * 2 + 0];
                float v1 = acc[mi][ni][half * 2 + 1];
                if (mode == 0) {
                    int b = m >> 10, t = m & (Tt - 1);
                    int h = ncol >> 7, d = ncol & (DK - 1);
                    if (proj == 0) {
                        size_t qi = (((size_t)(b * Hh + h) * Tt) + t) * DK + d;
                        *reinterpret_cast<__half2*>(g_qh + qi) =
                            __halves2half2(__float2half(v0 * RSQRT_DK),
                                           __float2half(v1 * RSQRT_DK));
                    } else {
                        float* base = (proj == 1) ? Kout : Vout;
                        float* dst = base + (((size_t)(b * Hh + h) * SS) + SC + t) * DK + d;
                        float2 vv; vv.x = v0; vv.y = v1;
                        *reinterpret_cast<float2*>(dst) = vv;
                    }
                } else {
                    float* dst = out + (size_t)m * Cc + ncol;
                    float2 vv; vv.x = v0; vv.y = v1;
                    *reinterpret_cast<float2*>(dst) = vv;
                }
            }
        }
    }
}

// ---------------------------------------------------------------------------
// Fused flash attention (R11 logic; now 2 CTAs/SM)
// ---------------------------------------------------------------------------
__global__ __launch_bounds__(256, 2)
void fa_kernel() {
    extern __shared__ char sm[];
    const uint32_t sbu = smem_u32(sm);
    const int tid = threadIdx.x;
    const int wid = tid >> 5, lane = tid & 31;
    const int gid = lane >> 2, tc = lane & 3;

    const int mt = 7 - blockIdx.x;
    const int bh = blockIdx.y;
    const int m0 = mt * 128;
    const int nst = (mt + 1) * 2;

    const __half* Qg = g_qh + (size_t)bh * Tt * DK + (size_t)m0 * DK;
    const __half* Kg = g_kc + (size_t)bh * SC * DK;
    const __half* Vg = g_vc + (size_t)bh * SC * DK;

    const uint32_t qs  = sbu;
    const uint32_t kvs = sbu + FA_QBYTES;

#pragma unroll
    for (int j = 0; j < 8; j++) {
        int c = j * 256 + tid;
        int row = c >> 4, col = c & 15;
        CP_ASYNC16(qs + row * FA_LDQ + col * 16, Qg + (size_t)row * DK + col * 8);
    }
    const __half* kvg[8];
    uint32_t kvo[8];
#pragma unroll
    for (int j = 0; j < 8; j++) {
        int c = j * 256 + tid;
        int mat = c >> 10;
        int idx = c & 1023;
        int row = idx >> 4, col = idx & 15;
        kvg[j] = (mat ? Vg : Kg) + (size_t)row * DK + col * 8;
        kvo[j] = (uint32_t)(mat * FA_KBYTES + row * FA_LDK + col * 16);
    }
#pragma unroll
    for (int j = 0; j < 8; j++) CP_ASYNC16(kvs + kvo[j], kvg[j]);
    CP_COMMIT();

    float acc_o[16][4];
#pragma unroll
    for (int nd = 0; nd < 16; nd++)
#pragma unroll
        for (int q = 0; q < 4; q++) acc_o[nd][q] = 0.f;

    float m0r = -1e30f, m1r = -1e30f, l0r = 0.f, l1r = 0.f;
    const int t0 = m0 + wid * 16 + gid;

    const uint32_t a_off = (uint32_t)((wid * 16 + (lane & 15)) * FA_LDQ + ((lane >> 4) << 4));
    const uint32_t b_off = (uint32_t)((lane & 7) * FA_LDK + (((lane >> 3) & 1) << 4));
    const uint32_t v_off = (uint32_t)((lane & 15) * FA_LDK);

    for (int i = 0; i < nst; i++) {
        const int s = i & 1;
        if (i + 1 < nst) {
            const uint32_t kv2 = kvs + ((i + 1) & 1) * FA_KV_STAGE;
            const size_t off = (size_t)(i + 1) * 64 * DK;
#pragma unroll
            for (int j = 0; j < 8; j++) CP_ASYNC16(kv2 + kvo[j], kvg[j] + off);
            CP_COMMIT();
            CP_WAIT(1);
        } else {
            CP_WAIT(0);
        }
        __syncthreads();

        const uint32_t kb_ = kvs + s * FA_KV_STAGE;
        const uint32_t vb_ = kb_ + FA_KBYTES;

        float acc_s[8][4];
#pragma unroll
        for (int ni = 0; ni < 8; ni++)
#pragma unroll
            for (int q = 0; q < 4; q++) acc_s[ni][q] = 0.f;
#pragma unroll
        for (int kk = 0; kk < 8; kk++) {
            uint32_t a_f[4];
            ldm_x4(qs + a_off + kk * 32, a_f);
#pragma unroll
            for (int ni = 0; ni < 8; ni++) {
                uint32_t b_f[2];
                ldm_x2(kb_ + b_off + ni * 8 * FA_LDK + kk * 32, b_f);
                mma_f16(acc_s[ni], a_f, b_f);
            }
        }

        if (i >= nst - 2) {
            const int sbase = i * 64;
#pragma unroll
            for (int ni = 0; ni < 8; ni++) {
#pragma unroll
                for (int q = 0; q < 4; q++) {
                    int sg = sbase + ni * 8 + tc * 2 + (q & 1);
                    int tt = t0 + ((q >> 1) << 3);
                    if (sg > tt) acc_s[ni][q] = -1e30f;
                }
            }
        }

        float mx0 = -1e30f, mx1 = -1e30f;
#pragma unroll
        for (int ni = 0; ni < 8; ni++) {
            mx0 = fmaxf(mx0, fmaxf(acc_s[ni][0], acc_s[ni][1]));
            mx1 = fmaxf(mx1, fmaxf(acc_s[ni][2], acc_s[ni][3]));
        }
        mx0 = fmaxf(mx0, __shfl_xor_sync(0xffffffffu, mx0, 1));
        mx0 = fmaxf(mx0, __shfl_xor_sync(0xffffffffu, mx0, 2));
        mx1 = fmaxf(mx1, __shfl_xor_sync(0xffffffffu, mx1, 1));
        mx1 = fmaxf(mx1, __shfl_xor_sync(0xffffffffu, mx1, 2));
        float nm0 = fmaxf(m0r, mx0), nm1 = fmaxf(m1r, mx1);
        float sc0 = __expf(m0r - nm0), sc1 = __expf(m1r - nm1);
        m0r = nm0; m1r = nm1;

        float sum0 = 0.f, sum1 = 0.f;
#pragma unroll
        for (int ni = 0; ni < 8; ni++) {
            acc_s[ni][0] = __expf(acc_s[ni][0] - m0r);
            acc_s[ni][1] = __expf(acc_s[ni][1] - m0r);
            acc_s[ni][2] = __expf(acc_s[ni][2] - m1r);
            acc_s[ni][3] = __expf(acc_s[ni][3] - m1r);
            sum0 += acc_s[ni][0] + acc_s[ni][1];
            sum1 += acc_s[ni][2] + acc_s[ni][3];
        }
        sum0 += __shfl_xor_sync(0xffffffffu, sum0, 1);
        sum0 += __shfl_xor_sync(0xffffffffu, sum0, 2);
        sum1 += __shfl_xor_sync(0xffffffffu, sum1, 1);
        sum1 += __shfl_xor_sync(0xffffffffu, sum1, 2);
        l0r = l0r * sc0 + sum0;
        l1r = l1r * sc1 + sum1;

#pragma unroll
        for (int nd = 0; nd < 16; nd++) {
            acc_o[nd][0] *= sc0; acc_o[nd][1] *= sc0;
            acc_o[nd][2] *= sc1; acc_o[nd][3] *= sc1;
        }

        uint32_t pf[4][4];
#pragma unroll
        for (int kk = 0; kk < 4; kk++) {
            pf[kk][0] = pack2h(acc_s[2 * kk][0],     acc_s[2 * kk][1]);
            pf[kk][1] = pack2h(acc_s[2 * kk][2],     acc_s[2 * kk][3]);
            pf[kk][2] = pack2h(acc_s[2 * kk + 1][0], acc_s[2 * kk + 1][1]);
            pf[kk][3] = pack2h(acc_s[2 * kk + 1][2], acc_s[2 * kk + 1][3]);
        }

#pragma unroll
        for (int kk = 0; kk < 4; kk++) {
#pragma unroll
            for (int nd = 0; nd < 16; nd++) {
                uint32_t b_f[2];
                ldm_x2_trans(vb_ + (kk * 16) * FA_LDK + v_off + nd * 16, b_f);
                mma_f16(acc_o[nd], pf[kk], b_f);
            }
        }
        __syncthreads();
    }

    const float inv0 = 1.f / l0r, inv1 = 1.f / l1r;
    const int b = bh >> 4, h = bh & (Hh - 1);
#pragma unroll
    for (int nd = 0; nd < 16; nd++) {
        int d = nd * 8 + tc * 2;
        size_t i0 = (((size_t)(b * Tt + t0) * Hh) + h) * DK + d;
        size_t i1 = (((size_t)(b * Tt + t0 + 8) * Hh) + h) * DK + d;
        *reinterpret_cast<__half2*>(g_ah + i0) =
            __halves2half2(__float2half(acc_o[nd][0] * inv0),
                           __float2half(acc_o[nd][1] * inv0));
        *reinterpret_cast<__half2*>(g_ah + i1) =
            __halves2half2(__float2half(acc_o[nd][2] * inv1),
                           __float2half(acc_o[nd][3] * inv1));
    }
}

// ---------------------------------------------------------------------------
extern "C" void kernel_launch(void* const* d_in, const int* in_sizes, int n_in,
                              void* d_out, int out_size) {
    const float* x  = (const float*)d_in[0];
    const float* ck = (const float*)d_in[1];
    const float* cv = (const float*)d_in[2];
    const float* Wq = (const float*)d_in[3];
    const float* Wk = (const float*)d_in[4];
    const float* Wv = (const float*)d_in[5];
    const float* Wo = (const float*)d_in[6];

    float* out  = (float*)d_out;
    float* Kout = out + (size_t)Bb * Tt * Cc;
    float* Vout = Kout + (size_t)Bb * Hh * SS * DK;

    cudaFuncSetAttribute(mm_hmma_kernel, cudaFuncAttributeMaxDynamicSharedMemorySize, MM_SMEM);
    cudaFuncSetAttribute(fa_kernel, cudaFuncAttributeMaxDynamicSharedMemorySize, FA_SMEM);

    convert7_kernel<<<28672, 256>>>((const float4*)x, (const float4*)Wq,
                                    (const float4*)Wk, (const float4*)Wv,
                                    (const float4*)Wo, (const float4*)ck,
                                    (const float4*)cv,
                                    (float4*)Kout, (float4*)Vout);
    mm_hmma_kernel<<<dim3(16, 16, 3), 256, MM_SMEM>>>(0, Kout, Vout, out);
    fa_kernel<<<dim3(8, 32), 256, FA_SMEM>>>();
    mm_hmma_kernel<<<dim3(16, 16, 1), 256, MM_SMEM>>>(1, Kout, Vout, out);
}

// round 15
// speedup vs baseline: 1.0735x; 1.0735x over previous
#include <cuda_runtime.h>
#include <cuda_fp16.h>
#include <math.h>
#include <stdint.h>

// Problem dims
#define Bb 2
#define Tt 1024
#define Cc 2048
#define Hh 16
#define DK 128
#define SC 1024
#define SS 2048
#define KDIM 2048
#define NMAT 4194304ull   // 2048*2048

#define RSQRT_DK 0.08838834764831845f

// HMMA GEMM tiling: CTA tile 128(M) x 128(N) x 64(K), 256 threads,
// 8 warps 2(m) x 4(n), warp tile 64x32. 2-stage pipeline, BK=64.
#define MM_BK 64
#define MM_LDS_B 144                       // bytes per smem row (64 fp16 + 16 pad)
#define MM_MATA 18432                      // 128 rows * 144
#define MM_STAGE (2 * MM_MATA)             // 36864 (A + B)
#define MM_SMEM (2 * MM_STAGE)             // 73728
#define MM_KSTEPS (KDIM / MM_BK)           // 32

// Flash-attention tiling: m-tile 128, s-tile 64, d=128, 8 warps (16 rows each)
#define FA_LDQ 272
#define FA_LDK 272
#define FA_QBYTES (128 * FA_LDQ)           // 34816
#define FA_KBYTES (64 * FA_LDK)            // 17408
#define FA_KV_STAGE (2 * FA_KBYTES)        // 34816
#define FA_SMEM (FA_QBYTES + 2 * FA_KV_STAGE)  // 104448

// ---------------------------------------------------------------------------
// Scratch (device globals)
// ---------------------------------------------------------------------------
__device__ __half g_xh[NMAT];                             // x fp16
__device__ __half g_w4[4 * NMAT];                         // Wq,Wk,Wv,Wo fp16
__device__ __half g_kc[NMAT];                             // cache_k fp16
__device__ __half g_vc[NMAT];                             // cache_v fp16
__device__ __half g_qh[NMAT];                             // Q fp16 [bh,t,d] scaled
__device__ __half g_ah[NMAT];                             // attn fp16 [b,t,h,d]

// ---------------------------------------------------------------------------
// PTX helpers
// ---------------------------------------------------------------------------
__device__ __forceinline__ uint32_t smem_u32(const void* p) {
    uint32_t a;
    asm("{ .reg .u64 t; cvta.to.shared.u64 t, %1; cvt.u32.u64 %0, t; }" : "=r"(a) : "l"(p));
    return a;
}
#define CP_ASYNC16(saddr, gaddr) \
    asm volatile("cp.async.cg.shared.global [%0], [%1], 16;" :: "r"(saddr), "l"(gaddr))
#define CP_COMMIT() asm volatile("cp.async.commit_group;" ::: "memory")
#define CP_WAIT(n)  asm volatile("cp.async.wait_group %0;" :: "n"(n) : "memory")

__device__ __forceinline__ void ldm_x4(uint32_t addr, uint32_t* r) {
    asm volatile("ldmatrix.sync.aligned.m8n8.x4.shared.b16 {%0,%1,%2,%3}, [%4];"
        : "=r"(r[0]), "=r"(r[1]), "=r"(r[2]), "=r"(r[3]) : "r"(addr));
}
__device__ __forceinline__ void ldm_x2(uint32_t addr, uint32_t* r) {
    asm volatile("ldmatrix.sync.aligned.m8n8.x2.shared.b16 {%0,%1}, [%2];"
        : "=r"(r[0]), "=r"(r[1]) : "r"(addr));
}
__device__ __forceinline__ void ldm_x2_trans(uint32_t addr, uint32_t* r) {
    asm volatile("ldmatrix.sync.aligned.m8n8.x2.trans.shared.b16 {%0,%1}, [%2];"
        : "=r"(r[0]), "=r"(r[1]) : "r"(addr));
}
__device__ __forceinline__ void mma_f16(float* d, const uint32_t* a, const uint32_t* b) {
    asm volatile("mma.sync.aligned.m16n8k16.row.col.f32.f16.f16.f32 "
        "{%0,%1,%2,%3}, {%4,%5,%6,%7}, {%8,%9}, {%0,%1,%2,%3};"
        : "+f"(d[0]), "+f"(d[1]), "+f"(d[2]), "+f"(d[3])
        : "r"(a[0]), "r"(a[1]), "r"(a[2]), "r"(a[3]), "r"(b[0]), "r"(b[1]));
}
__device__ __forceinline__ uint32_t pack2h(float a, float b) {
    __half2 h = __floats2half2_rn(a, b);
    return *reinterpret_cast<uint32_t*>(&h);
}

// ---------------------------------------------------------------------------
// convert_xw: x -> fp16 (g_xh), Wq/Wk/Wv/Wo -> fp16 (g_w4). 5 matrices.
// ---------------------------------------------------------------------------
__global__ void convert_xw_kernel(const float4* __restrict__ x,
                                  const float4* __restrict__ wq,
                                  const float4* __restrict__ wk,
                                  const float4* __restrict__ wv,
                                  const float4* __restrict__ wo) {
    int id = blockIdx.x * blockDim.x + threadIdx.x;
    const int per = (int)(NMAT / 4);
    int mat = id / per;
    int rem = id - mat * per;
    const float4* srcs[5] = {x, wq, wk, wv, wo};
    float4 v = srcs[mat][rem];
    __half* base = (mat == 0) ? g_xh : (g_w4 + (size_t)(mat - 1) * NMAT);
    __half2* d = reinterpret_cast<__half2*>(base) + rem * 2;
    d[0] = __halves2half2(__float2half(v.x), __float2half(v.y));
    d[1] = __halves2half2(__float2half(v.z), __float2half(v.w));
}

// ---------------------------------------------------------------------------
// convert_kv: ck/cv -> fp16 (g_kc/g_vc) AND fp32 copy into output K/V slots.
// Runs on a forked stream, overlapped with mm0.
// ---------------------------------------------------------------------------
__global__ void convert_kv_kernel(const float4* __restrict__ ck,
                                  const float4* __restrict__ cv,
                                  float4* __restrict__ Kout,
                                  float4* __restrict__ Vout) {
    int id = blockIdx.x * blockDim.x + threadIdx.x;
    const int per = (int)(NMAT / 4);
    int mat = id / per;              // 0 = K, 1 = V
    int rem = id - mat * per;
    float4 v = (mat ? cv : ck)[rem];
    __half* base = mat ? g_vc : g_kc;
    __half2* d = reinterpret_cast<__half2*>(base) + rem * 2;
    d[0] = __halves2half2(__float2half(v.x), __float2half(v.y));
    d[1] = __halves2half2(__float2half(v.z), __float2half(v.w));
    int pos = rem & 31;
    int row = rem >> 5;
    int s = row & (SC - 1);
    int bh = row >> 10;
    int dst = (((bh * SS) + s) << 5) + pos;
    (mat ? Vout : Kout)[dst] = v;
}

// ---------------------------------------------------------------------------
// HMMA fp16 GEMM (256 threads, 8 warps 2x4, CTA 128x128, BK=64, 2-stage)
// ---------------------------------------------------------------------------
__global__ __launch_bounds__(256, 2)
void mm_hmma_kernel(int mode, float* __restrict__ Kout, float* __restrict__ Vout,
                    float* __restrict__ out) {
    extern __shared__ char sm[];
    const uint32_t sbu = smem_u32(sm);
    const int tid = threadIdx.x;
    const int wid = tid >> 5, lane = tid & 31;
    const int warp_m = wid >> 2;          // 0..1
    const int warp_n = wid & 3;           // 0..3

    const int proj = blockIdx.z;
    const __half *As, *Bs;
    if (mode == 0) {
        As = g_xh;
        Bs = g_w4 + (size_t)proj * NMAT;
    } else {
        As = g_ah;
        Bs = g_w4 + (size_t)3 * NMAT;
    }
    const int m0 = blockIdx.x * 128, n0 = blockIdx.y * 128;

    const __half* gptr[8];
    uint32_t soff[8];
#pragma unroll
    for (int j = 0; j < 8; j++) {
        int c = j * 256 + tid;
        int idx = c & 1023;
        int r = idx >> 3, c8 = idx & 7;
        if (c < 1024) {
            gptr[j] = As + (size_t)(m0 + r) * KDIM + c8 * 8;
            soff[j] = (uint32_t)(r * MM_LDS_B + c8 * 16);
        } else {
            gptr[j] = Bs + (size_t)(n0 + r) * KDIM + c8 * 8;
            soff[j] = (uint32_t)(MM_MATA + r * MM_LDS_B + c8 * 16);
        }
    }

    const uint32_t a_row  = (uint32_t)(warp_m * 64 + (lane & 15));
    const uint32_t a_kb   = (uint32_t)(((lane >> 4) << 3) * 2);
    const uint32_t b_row4 = (uint32_t)(warp_n * 32 + (lane & 7) + ((lane >> 4) << 3));
    const uint32_t b_kb4  = (uint32_t)(((lane >> 3) & 1) << 4);

    float acc[4][4][4];
#pragma unroll
    for (int mi = 0; mi < 4; mi++)
#pragma unroll
        for (int ni = 0; ni < 4; ni++)
#pragma unroll
            for (int q = 0; q < 4; q++) acc[mi][ni][q] = 0.f;

#pragma unroll
    for (int j = 0; j < 8; j++) CP_ASYNC16(sbu + soff[j], gptr[j]);
    CP_COMMIT();

    for (int i = 0; i < MM_KSTEPS; i++) {
        __syncthreads();
        if (i + 1 < MM_KSTEPS) {
            const uint32_t sb2 = sbu + ((i + 1) & 1) * MM_STAGE;
            const int k0 = (i + 1) * MM_BK;
#pragma unroll
            for (int j = 0; j < 8; j++) CP_ASYNC16(sb2 + soff[j], gptr[j] + k0);
            CP_COMMIT();
            CP_WAIT(1);
        } else {
            CP_WAIT(0);
        }
        __syncthreads();

        const uint32_t stage = sbu + (i & 1) * MM_STAGE;
#pragma unroll
        for (int kk = 0; kk < 4; kk++) {
            const uint32_t kb = (uint32_t)(kk * 32);
            uint32_t a_f[4][4], b4[2][4];
#pragma unroll
            for (int nj = 0; nj < 2; nj++) {
                uint32_t baddr = stage + MM_MATA +
                                 (b_row4 + nj * 16) * MM_LDS_B + b_kb4 + kb;
                ldm_x4(baddr, b4[nj]);
            }
#pragma unroll
            for (int mi = 0; mi < 4; mi++) {
                uint32_t aaddr = stage + (a_row + mi * 16) * MM_LDS_B + a_kb + kb;
                ldm_x4(aaddr, a_f[mi]);
            }
#pragma unroll
            for (int mi = 0; mi < 4; mi++)
#pragma unroll
                for (int ni = 0; ni < 4; ni++)
                    mma_f16(acc[mi][ni], a_f[mi], &b4[ni >> 1][(ni & 1) * 2]);
        }
    }

    const int gid = lane >> 2, tc = lane & 3;
#pragma unroll
    for (int mi = 0; mi < 4; mi++) {
#pragma unroll
        for (int ni = 0; ni < 4; ni++) {
            int mrow0 = m0 + warp_m * 64 + mi * 16 + gid;
            int ncol  = n0 + warp_n * 32 + ni * 8 + tc * 2;
#pragma unroll
            for (int half = 0; half < 2; half++) {
                int m = mrow0 + half * 8;
                float v0 = acc[mi][ni][half * 2 + 0];
                float v1 = acc[mi][ni][half * 2 + 1];
                if (mode == 0) {
                    int b = m >> 10, t = m & (Tt - 1);
                    int h = ncol >> 7, d = ncol & (DK - 1);
                    if (proj == 0) {
                        size_t qi = (((size_t)(b * Hh + h) * Tt) + t) * DK + d;
                        *reinterpret_cast<__half2*>(g_qh + qi) =
                            __halves2half2(__float2half(v0 * RSQRT_DK),
                                           __float2half(v1 * RSQRT_DK));
                    } else {
                        float* base = (proj == 1) ? Kout : Vout;
                        float* dst = base + (((size_t)(b * Hh + h) * SS) + SC + t) * DK + d;
                        float2 vv; vv.x = v0; vv.y = v1;
                        *reinterpret_cast<float2*>(dst) = vv;
                    }
                } else {
                    float* dst = out + (size_t)m * Cc + ncol;
                    float2 vv; vv.x = v0; vv.y = v1;
                    *reinterpret_cast<float2*>(dst) = vv;
                }
            }
        }
    }
}

// ---------------------------------------------------------------------------
// Fused flash attention (R13 config: occupancy 1)
// ---------------------------------------------------------------------------
__global__ __launch_bounds__(256, 1)
void fa_kernel() {
    extern __shared__ char sm[];
    const uint32_t sbu = smem_u32(sm);
    const int tid = threadIdx.x;
    const int wid = tid >> 5, lane = tid & 31;
    const int gid = lane >> 2, tc = lane & 3;

    const int mt = 7 - blockIdx.x;
    const int bh = blockIdx.y;
    const int m0 = mt * 128;
    const int nst = (mt + 1) * 2;

    const __half* Qg = g_qh + (size_t)bh * Tt * DK + (size_t)m0 * DK;
    const __half* Kg = g_kc + (size_t)bh * SC * DK;
    const __half* Vg = g_vc + (size_t)bh * SC * DK;

    const uint32_t qs  = sbu;
    const uint32_t kvs = sbu + FA_QBYTES;

#pragma unroll
    for (int j = 0; j < 8; j++) {
        int c = j * 256 + tid;
        int row = c >> 4, col = c & 15;
        CP_ASYNC16(qs + row * FA_LDQ + col * 16, Qg + (size_t)row * DK + col * 8);
    }
    const __half* kvg[8];
    uint32_t kvo[8];
#pragma unroll
    for (int j = 0; j < 8; j++) {
        int c = j * 256 + tid;
        int mat = c >> 10;
        int idx = c & 1023;
        int row = idx >> 4, col = idx & 15;
        kvg[j] = (mat ? Vg : Kg) + (size_t)row * DK + col * 8;
        kvo[j] = (uint32_t)(mat * FA_KBYTES + row * FA_LDK + col * 16);
    }
#pragma unroll
    for (int j = 0; j < 8; j++) CP_ASYNC16(kvs + kvo[j], kvg[j]);
    CP_COMMIT();

    float acc_o[16][4];
#pragma unroll
    for (int nd = 0; nd < 16; nd++)
#pragma unroll
        for (int q = 0; q < 4; q++) acc_o[nd][q] = 0.f;

    float m0r = -1e30f, m1r = -1e30f, l0r = 0.f, l1r = 0.f;
    const int t0 = m0 + wid * 16 + gid;

    const uint32_t a_off = (uint32_t)((wid * 16 + (lane & 15)) * FA_LDQ + ((lane >> 4) << 4));
    const uint32_t b_off = (uint32_t)((lane & 7) * FA_LDK + (((lane >> 3) & 1) << 4));
    const uint32_t v_off = (uint32_t)((lane & 15) * FA_LDK);

    for (int i = 0; i < nst; i++) {
        const int s = i & 1;
        if (i + 1 < nst) {
            const uint32_t kv2 = kvs + ((i + 1) & 1) * FA_KV_STAGE;
            const size_t off = (size_t)(i + 1) * 64 * DK;
#pragma unroll
            for (int j = 0; j < 8; j++) CP_ASYNC16(kv2 + kvo[j], kvg[j] + off);
            CP_COMMIT();
            CP_WAIT(1);
        } else {
            CP_WAIT(0);
        }
        __syncthreads();

        const uint32_t kb_ = kvs + s * FA_KV_STAGE;
        const uint32_t vb_ = kb_ + FA_KBYTES;

        float acc_s[8][4];
#pragma unroll
        for (int ni = 0; ni < 8; ni++)
#pragma unroll
            for (int q = 0; q < 4; q++) acc_s[ni][q] = 0.f;
#pragma unroll
        for (int kk = 0; kk < 8; kk++) {
            uint32_t a_f[4];
            ldm_x4(qs + a_off + kk * 32, a_f);
#pragma unroll
            for (int ni = 0; ni < 8; ni++) {
                uint32_t b_f[2];
                ldm_x2(kb_ + b_off + ni * 8 * FA_LDK + kk * 32, b_f);
                mma_f16(acc_s[ni], a_f, b_f);
            }
        }

        if (i >= nst - 2) {
            const int sbase = i * 64;
#pragma unroll
            for (int ni = 0; ni < 8; ni++) {
#pragma unroll
                for (int q = 0; q < 4; q++) {
                    int sg = sbase + ni * 8 + tc * 2 + (q & 1);
                    int tt = t0 + ((q >> 1) << 3);
                    if (sg > tt) acc_s[ni][q] = -1e30f;
                }
            }
        }

        float mx0 = -1e30f, mx1 = -1e30f;
#pragma unroll
        for (int ni = 0; ni < 8; ni++) {
            mx0 = fmaxf(mx0, fmaxf(acc_s[ni][0], acc_s[ni][1]));
            mx1 = fmaxf(mx1, fmaxf(acc_s[ni][2], acc_s[ni][3]));
        }
        mx0 = fmaxf(mx0, __shfl_xor_sync(0xffffffffu, mx0, 1));
        mx0 = fmaxf(mx0, __shfl_xor_sync(0xffffffffu, mx0, 2));
        mx1 = fmaxf(mx1, __shfl_xor_sync(0xffffffffu, mx1, 1));
        mx1 = fmaxf(mx1, __shfl_xor_sync(0xffffffffu, mx1, 2));
        float nm0 = fmaxf(m0r, mx0), nm1 = fmaxf(m1r, mx1);
        float sc0 = __expf(m0r - nm0), sc1 = __expf(m1r - nm1);
        m0r = nm0; m1r = nm1;

        float sum0 = 0.f, sum1 = 0.f;
#pragma unroll
        for (int ni = 0; ni < 8; ni++) {
            acc_s[ni][0] = __expf(acc_s[ni][0] - m0r);
            acc_s[ni][1] = __expf(acc_s[ni][1] - m0r);
            acc_s[ni][2] = __expf(acc_s[ni][2] - m1r);
            acc_s[ni][3] = __expf(acc_s[ni][3] - m1r);
            sum0 += acc_s[ni][0] + acc_s[ni][1];
            sum1 += acc_s[ni][2] + acc_s[ni][3];
        }
        sum0 += __shfl_xor_sync(0xffffffffu, sum0, 1);
        sum0 += __shfl_xor_sync(0xffffffffu, sum0, 2);
        sum1 += __shfl_xor_sync(0xffffffffu, sum1, 1);
        sum1 += __shfl_xor_sync(0xffffffffu, sum1, 2);
        l0r = l0r * sc0 + sum0;
        l1r = l1r * sc1 + sum1;

#pragma unroll
        for (int nd = 0; nd < 16; nd++) {
            acc_o[nd][0] *= sc0; acc_o[nd][1] *= sc0;
            acc_o[nd][2] *= sc1; acc_o[nd][3] *= sc1;
        }

        uint32_t pf[4][4];
#pragma unroll
        for (int kk = 0; kk < 4; kk++) {
            pf[kk][0] = pack2h(acc_s[2 * kk][0],     acc_s[2 * kk][1]);
            pf[kk][1] = pack2h(acc_s[2 * kk][2],     acc_s[2 * kk][3]);
            pf[kk][2] = pack2h(acc_s[2 * kk + 1][0], acc_s[2 * kk + 1][1]);
            pf[kk][3] = pack2h(acc_s[2 * kk + 1][2], acc_s[2 * kk + 1][3]);
        }

#pragma unroll
        for (int kk = 0; kk < 4; kk++) {
#pragma unroll
            for (int nd = 0; nd < 16; nd++) {
                uint32_t b_f[2];
                ldm_x2_trans(vb_ + (kk * 16) * FA_LDK + v_off + nd * 16, b_f);
                mma_f16(acc_o[nd], pf[kk], b_f);
            }
        }
        __syncthreads();
    }

    const float inv0 = 1.f / l0r, inv1 = 1.f / l1r;
    const int b = bh >> 4, h = bh & (Hh - 1);
#pragma unroll
    for (int nd = 0; nd < 16; nd++) {
        int d = nd * 8 + tc * 2;
        size_t i0 = (((size_t)(b * Tt + t0) * Hh) + h) * DK + d;
        size_t i1 = (((size_t)(b * Tt + t0 + 8) * Hh) + h) * DK + d;
        *reinterpret_cast<__half2*>(g_ah + i0) =
            __halves2half2(__float2half(acc_o[nd][0] * inv0),
                           __float2half(acc_o[nd][1] * inv0));
        *reinterpret_cast<__half2*>(g_ah + i1) =
            __halves2half2(__float2half(acc_o[nd][2] * inv1),
                           __float2half(acc_o[nd][3] * inv1));
    }
}

// ---------------------------------------------------------------------------
extern "C" void kernel_launch(void* const* d_in, const int* in_sizes, int n_in,
                              void* d_out, int out_size) {
    const float* x  = (const float*)d_in[0];
    const float* ck = (const float*)d_in[1];
    const float* cv = (const float*)d_in[2];
    const float* Wq = (const float*)d_in[3];
    const float* Wk = (const float*)d_in[4];
    const float* Wv = (const float*)d_in[5];
    const float* Wo = (const float*)d_in[6];

    float* out  = (float*)d_out;
    float* Kout = out + (size_t)Bb * Tt * Cc;
    float* Vout = Kout + (size_t)Bb * Hh * SS * DK;

    // One-time resources (created during the uncaptured correctness call)
    static cudaStream_t s1 = nullptr;
    static cudaEvent_t evFork = nullptr, evJoin = nullptr;
    if (s1 == nullptr) {
        cudaStreamCreateWithFlags(&s1, cudaStreamNonBlocking);
        cudaEventCreateWithFlags(&evFork, cudaEventDisableTiming);
        cudaEventCreateWithFlags(&evJoin, cudaEventDisableTiming);
        cudaFuncSetAttribute(mm_hmma_kernel, cudaFuncAttributeMaxDynamicSharedMemorySize, MM_SMEM);
        cudaFuncSetAttribute(fa_kernel, cudaFuncAttributeMaxDynamicSharedMemorySize, FA_SMEM);
    }

    // fork: cache convert/copy runs concurrently with conv_xw + mm0
    cudaEventRecord(evFork, 0);
    cudaStreamWaitEvent(s1, evFork, 0);
    convert_kv_kernel<<<8192, 256, 0, s1>>>((const float4*)ck, (const float4*)cv,
                                            (float4*)Kout, (float4*)Vout);
    cudaEventRecord(evJoin, s1);

    // main stream: weights/x convert -> QKV projections
    convert_xw_kernel<<<20480, 256>>>((const float4*)x, (const float4*)Wq,
                                      (const float4*)Wk, (const float4*)Wv,
                                      (const float4*)Wo);
    mm_hmma_kernel<<<dim3(16, 16, 3), 256, MM_SMEM>>>(0, Kout, Vout, out);

    // join: fa needs g_kc/g_vc from the forked stream
    cudaStreamWaitEvent(0, evJoin, 0);
    fa_kernel<<<dim3(8, 32), 256, FA_SMEM>>>();
    mm_hmma_kernel<<<dim3(16, 16, 1), 256, MM_SMEM>>>(1, Kout, Vout, out);
}

// round 16
// speedup vs baseline: 1.1675x; 1.0876x over previous
#include <cuda_runtime.h>
#include <cuda_fp16.h>
#include <math.h>
#include <stdint.h>

// Problem dims
#define Bb 2
#define Tt 1024
#define Cc 2048
#define Hh 16
#define DK 128
#define SC 1024
#define SS 2048
#define KDIM 2048
#define NMAT 4194304ull   // 2048*2048

#define RSQRT_DK 0.08838834764831845f

// HMMA GEMM tiling: CTA tile 128(M) x 128(N) x 64(K), 256 threads,
// 8 warps 2(m) x 4(n), warp tile 64x32. 2-stage pipeline, BK=64.
#define MM_BK 64
#define MM_LDS_B 144                       // bytes per smem row (64 fp16 + 16 pad)
#define MM_MATA 18432                      // 128 rows * 144
#define MM_STAGE (2 * MM_MATA)             // 36864 (A + B)
#define MM_SMEM (2 * MM_STAGE)             // 73728
#define MM_KSTEPS (KDIM / MM_BK)           // 32

// Flash-attention tiling: m-tile 128, s-tile 64, d=128, 8 warps (16 rows each)
#define FA_LDQ 272
#define FA_LDK 272
#define FA_QBYTES (128 * FA_LDQ)           // 34816
#define FA_KBYTES (64 * FA_LDK)            // 17408
#define FA_KV_STAGE (2 * FA_KBYTES)        // 34816
#define FA_SMEM (FA_QBYTES + 2 * FA_KV_STAGE)  // 104448

// ---------------------------------------------------------------------------
// Scratch (device globals)
// ---------------------------------------------------------------------------
__device__ __half g_xh[NMAT];                             // x fp16
__device__ __half g_w4[4 * NMAT];                         // Wq,Wk,Wv,Wo fp16
__device__ __half g_kc[NMAT];                             // cache_k fp16
__device__ __half g_vc[NMAT];                             // cache_v fp16
__device__ __half g_qh[NMAT];                             // Q fp16 [bh,t,d] scaled
__device__ __half g_ah[NMAT];                             // attn fp16 [b,t,h,d]

// ---------------------------------------------------------------------------
// PTX helpers
// ---------------------------------------------------------------------------
__device__ __forceinline__ uint32_t smem_u32(const void* p) {
    uint32_t a;
    asm("{ .reg .u64 t; cvta.to.shared.u64 t, %1; cvt.u32.u64 %0, t; }" : "=r"(a) : "l"(p));
    return a;
}
#define CP_ASYNC16(saddr, gaddr) \
    asm volatile("cp.async.cg.shared.global [%0], [%1], 16;" :: "r"(saddr), "l"(gaddr))
#define CP_COMMIT() asm volatile("cp.async.commit_group;" ::: "memory")
#define CP_WAIT(n)  asm volatile("cp.async.wait_group %0;" :: "n"(n) : "memory")

__device__ __forceinline__ void ldm_x4(uint32_t addr, uint32_t* r) {
    asm volatile("ldmatrix.sync.aligned.m8n8.x4.shared.b16 {%0,%1,%2,%3}, [%4];"
        : "=r"(r[0]), "=r"(r[1]), "=r"(r[2]), "=r"(r[3]) : "r"(addr));
}
__device__ __forceinline__ void ldm_x2(uint32_t addr, uint32_t* r) {
    asm volatile("ldmatrix.sync.aligned.m8n8.x2.shared.b16 {%0,%1}, [%2];"
        : "=r"(r[0]), "=r"(r[1]) : "r"(addr));
}
__device__ __forceinline__ void ldm_x2_trans(uint32_t addr, uint32_t* r) {
    asm volatile("ldmatrix.sync.aligned.m8n8.x2.trans.shared.b16 {%0,%1}, [%2];"
        : "=r"(r[0]), "=r"(r[1]) : "r"(addr));
}
__device__ __forceinline__ void mma_f16(float* d, const uint32_t* a, const uint32_t* b) {
    asm volatile("mma.sync.aligned.m16n8k16.row.col.f32.f16.f16.f32 "
        "{%0,%1,%2,%3}, {%4,%5,%6,%7}, {%8,%9}, {%0,%1,%2,%3};"
        : "+f"(d[0]), "+f"(d[1]), "+f"(d[2]), "+f"(d[3])
        : "r"(a[0]), "r"(a[1]), "r"(a[2]), "r"(a[3]), "r"(b[0]), "r"(b[1]));
}
__device__ __forceinline__ uint32_t pack2h(float a, float b) {
    __half2 h = __floats2half2_rn(a, b);
    return *reinterpret_cast<uint32_t*>(&h);
}

// ---------------------------------------------------------------------------
// convert_xw: x -> fp16 (g_xh), Wq/Wk/Wv/Wo -> fp16 (g_w4). 5 matrices.
// ---------------------------------------------------------------------------
__global__ void convert_xw_kernel(const float4* __restrict__ x,
                                  const float4* __restrict__ wq,
                                  const float4* __restrict__ wk,
                                  const float4* __restrict__ wv,
                                  const float4* __restrict__ wo) {
    int id = blockIdx.x * blockDim.x + threadIdx.x;
    const int per = (int)(NMAT / 4);
    int mat = id / per;
    int rem = id - mat * per;
    const float4* srcs[5] = {x, wq, wk, wv, wo};
    float4 v = srcs[mat][rem];
    __half* base = (mat == 0) ? g_xh : (g_w4 + (size_t)(mat - 1) * NMAT);
    __half2* d = reinterpret_cast<__half2*>(base) + rem * 2;
    d[0] = __halves2half2(__float2half(v.x), __float2half(v.y));
    d[1] = __halves2half2(__float2half(v.z), __float2half(v.w));
}

// ---------------------------------------------------------------------------
// convert_kv: ck/cv -> fp16 AND fp32 copy into output K/V slots (forked stream)
// ---------------------------------------------------------------------------
__global__ void convert_kv_kernel(const float4* __restrict__ ck,
                                  const float4* __restrict__ cv,
                                  float4* __restrict__ Kout,
                                  float4* __restrict__ Vout) {
    int id = blockIdx.x * blockDim.x + threadIdx.x;
    const int per = (int)(NMAT / 4);
    int mat = id / per;              // 0 = K, 1 = V
    int rem = id - mat * per;
    float4 v = (mat ? cv : ck)[rem];
    __half* base = mat ? g_vc : g_kc;
    __half2* d = reinterpret_cast<__half2*>(base) + rem * 2;
    d[0] = __halves2half2(__float2half(v.x), __float2half(v.y));
    d[1] = __halves2half2(__float2half(v.z), __float2half(v.w));
    int pos = rem & 31;
    int row = rem >> 5;
    int s = row & (SC - 1);
    int bh = row >> 10;
    int dst = (((bh * SS) + s) << 5) + pos;
    (mat ? Vout : Kout)[dst] = v;
}

// ---------------------------------------------------------------------------
// HMMA fp16 GEMM (256 threads, 8 warps 2x4, CTA 128x128, BK=64, 2-stage)
// mode 0: A=x, B=W[pbase+blockIdx.z]; proj0 -> Q fp16, proj1/2 -> K/V fp32
// mode 1: A=attn, B=Wo; -> out fp32
// ---------------------------------------------------------------------------
__global__ __launch_bounds__(256, 2)
void mm_hmma_kernel(int mode, int pbase, float* __restrict__ Kout,
                    float* __restrict__ Vout, float* __restrict__ out) {
    extern __shared__ char sm[];
    const uint32_t sbu = smem_u32(sm);
    const int tid = threadIdx.x;
    const int wid = tid >> 5, lane = tid & 31;
    const int warp_m = wid >> 2;          // 0..1
    const int warp_n = wid & 3;           // 0..3

    const int proj = pbase + blockIdx.z;
    const __half *As, *Bs;
    if (mode == 0) {
        As = g_xh;
        Bs = g_w4 + (size_t)proj * NMAT;
    } else {
        As = g_ah;
        Bs = g_w4 + (size_t)3 * NMAT;
    }
    const int m0 = blockIdx.x * 128, n0 = blockIdx.y * 128;

    const __half* gptr[8];
    uint32_t soff[8];
#pragma unroll
    for (int j = 0; j < 8; j++) {
        int c = j * 256 + tid;
        int idx = c & 1023;
        int r = idx >> 3, c8 = idx & 7;
        if (c < 1024) {
            gptr[j] = As + (size_t)(m0 + r) * KDIM + c8 * 8;
            soff[j] = (uint32_t)(r * MM_LDS_B + c8 * 16);
        } else {
            gptr[j] = Bs + (size_t)(n0 + r) * KDIM + c8 * 8;
            soff[j] = (uint32_t)(MM_MATA + r * MM_LDS_B + c8 * 16);
        }
    }

    const uint32_t a_row  = (uint32_t)(warp_m * 64 + (lane & 15));
    const uint32_t a_kb   = (uint32_t)(((lane >> 4) << 3) * 2);
    const uint32_t b_row4 = (uint32_t)(warp_n * 32 + (lane & 7) + ((lane >> 4) << 3));
    const uint32_t b_kb4  = (uint32_t)(((lane >> 3) & 1) << 4);

    float acc[4][4][4];
#pragma unroll
    for (int mi = 0; mi < 4; mi++)
#pragma unroll
        for (int ni = 0; ni < 4; ni++)
#pragma unroll
            for (int q = 0; q < 4; q++) acc[mi][ni][q] = 0.f;

#pragma unroll
    for (int j = 0; j < 8; j++) CP_ASYNC16(sbu + soff[j], gptr[j]);
    CP_COMMIT();

    for (int i = 0; i < MM_KSTEPS; i++) {
        __syncthreads();
        if (i + 1 < MM_KSTEPS) {
            const uint32_t sb2 = sbu + ((i + 1) & 1) * MM_STAGE;
            const int k0 = (i + 1) * MM_BK;
#pragma unroll
            for (int j = 0; j < 8; j++) CP_ASYNC16(sb2 + soff[j], gptr[j] + k0);
            CP_COMMIT();
            CP_WAIT(1);
        } else {
            CP_WAIT(0);
        }
        __syncthreads();

        const uint32_t stage = sbu + (i & 1) * MM_STAGE;
#pragma unroll
        for (int kk = 0; kk < 4; kk++) {
            const uint32_t kb = (uint32_t)(kk * 32);
            uint32_t a_f[4][4], b4[2][4];
#pragma unroll
            for (int nj = 0; nj < 2; nj++) {
                uint32_t baddr = stage + MM_MATA +
                                 (b_row4 + nj * 16) * MM_LDS_B + b_kb4 + kb;
                ldm_x4(baddr, b4[nj]);
            }
#pragma unroll
            for (int mi = 0; mi < 4; mi++) {
                uint32_t aaddr = stage + (a_row + mi * 16) * MM_LDS_B + a_kb + kb;
                ldm_x4(aaddr, a_f[mi]);
            }
#pragma unroll
            for (int mi = 0; mi < 4; mi++)
#pragma unroll
                for (int ni = 0; ni < 4; ni++)
                    mma_f16(acc[mi][ni], a_f[mi], &b4[ni >> 1][(ni & 1) * 2]);
        }
    }

    const int gid = lane >> 2, tc = lane & 3;
#pragma unroll
    for (int mi = 0; mi < 4; mi++) {
#pragma unroll
        for (int ni = 0; ni < 4; ni++) {
            int mrow0 = m0 + warp_m * 64 + mi * 16 + gid;
            int ncol  = n0 + warp_n * 32 + ni * 8 + tc * 2;
#pragma unroll
            for (int half = 0; half < 2; half++) {
                int m = mrow0 + half * 8;
                float v0 = acc[mi][ni][half * 2 + 0];
                float v1 = acc[mi][ni][half * 2 + 1];
                if (mode == 0) {
                    int b = m >> 10, t = m & (Tt - 1);
                    int h = ncol >> 7, d = ncol & (DK - 1);
                    if (proj == 0) {
                        size_t qi = (((size_t)(b * Hh + h) * Tt) + t) * DK + d;
                        *reinterpret_cast<__half2*>(g_qh + qi) =
                            __halves2half2(__float2half(v0 * RSQRT_DK),
                                           __float2half(v1 * RSQRT_DK));
                    } else {
                        float* base = (proj == 1) ? Kout : Vout;
                        float* dst = base + (((size_t)(b * Hh + h) * SS) + SC + t) * DK + d;
                        float2 vv; vv.x = v0; vv.y = v1;
                        *reinterpret_cast<float2*>(dst) = vv;
                    }
                } else {
                    float* dst = out + (size_t)m * Cc + ncol;
                    float2 vv; vv.x = v0; vv.y = v1;
                    *reinterpret_cast<float2*>(dst) = vv;
                }
            }
        }
    }
}

// ---------------------------------------------------------------------------
// Fused flash attention (occupancy 1)
// ---------------------------------------------------------------------------
__global__ __launch_bounds__(256, 1)
void fa_kernel() {
    extern __shared__ char sm[];
    const uint32_t sbu = smem_u32(sm);
    const int tid = threadIdx.x;
    const int wid = tid >> 5, lane = tid & 31;
    const int gid = lane >> 2, tc = lane & 3;

    const int mt = 7 - blockIdx.x;
    const int bh = blockIdx.y;
    const int m0 = mt * 128;
    const int nst = (mt + 1) * 2;

    const __half* Qg = g_qh + (size_t)bh * Tt * DK + (size_t)m0 * DK;
    const __half* Kg = g_kc + (size_t)bh * SC * DK;
    const __half* Vg = g_vc + (size_t)bh * SC * DK;

    const uint32_t qs  = sbu;
    const uint32_t kvs = sbu + FA_QBYTES;

#pragma unroll
    for (int j = 0; j < 8; j++) {
        int c = j * 256 + tid;
        int row = c >> 4, col = c & 15;
        CP_ASYNC16(qs + row * FA_LDQ + col * 16, Qg + (size_t)row * DK + col * 8);
    }
    const __half* kvg[8];
    uint32_t kvo[8];
#pragma unroll
    for (int j = 0; j < 8; j++) {
        int c = j * 256 + tid;
        int mat = c >> 10;
        int idx = c & 1023;
        int row = idx >> 4, col = idx & 15;
        kvg[j] = (mat ? Vg : Kg) + (size_t)row * DK + col * 8;
        kvo[j] = (uint32_t)(mat * FA_KBYTES + row * FA_LDK + col * 16);
    }
#pragma unroll
    for (int j = 0; j < 8; j++) CP_ASYNC16(kvs + kvo[j], kvg[j]);
    CP_COMMIT();

    float acc_o[16][4];
#pragma unroll
    for (int nd = 0; nd < 16; nd++)
#pragma unroll
        for (int q = 0; q < 4; q++) acc_o[nd][q] = 0.f;

    float m0r = -1e30f, m1r = -1e30f, l0r = 0.f, l1r = 0.f;
    const int t0 = m0 + wid * 16 + gid;

    const uint32_t a_off = (uint32_t)((wid * 16 + (lane & 15)) * FA_LDQ + ((lane >> 4) << 4));
    const uint32_t b_off = (uint32_t)((lane & 7) * FA_LDK + (((lane >> 3) & 1) << 4));
    const uint32_t v_off = (uint32_t)((lane & 15) * FA_LDK);

    for (int i = 0; i < nst; i++) {
        const int s = i & 1;
        if (i + 1 < nst) {
            const uint32_t kv2 = kvs + ((i + 1) & 1) * FA_KV_STAGE;
            const size_t off = (size_t)(i + 1) * 64 * DK;
#pragma unroll
            for (int j = 0; j < 8; j++) CP_ASYNC16(kv2 + kvo[j], kvg[j] + off);
            CP_COMMIT();
            CP_WAIT(1);
        } else {
            CP_WAIT(0);
        }
        __syncthreads();

        const uint32_t kb_ = kvs + s * FA_KV_STAGE;
        const uint32_t vb_ = kb_ + FA_KBYTES;

        float acc_s[8][4];
#pragma unroll
        for (int ni = 0; ni < 8; ni++)
#pragma unroll
            for (int q = 0; q < 4; q++) acc_s[ni][q] = 0.f;
#pragma unroll
        for (int kk = 0; kk < 8; kk++) {
            uint32_t a_f[4];
            ldm_x4(qs + a_off + kk * 32, a_f);
#pragma unroll
            for (int ni = 0; ni < 8; ni++) {
                uint32_t b_f[2];
                ldm_x2(kb_ + b_off + ni * 8 * FA_LDK + kk * 32, b_f);
                mma_f16(acc_s[ni], a_f, b_f);
            }
        }

        if (i >= nst - 2) {
            const int sbase = i * 64;
#pragma unroll
            for (int ni = 0; ni < 8; ni++) {
#pragma unroll
                for (int q = 0; q < 4; q++) {
                    int sg = sbase + ni * 8 + tc * 2 + (q & 1);
                    int tt = t0 + ((q >> 1) << 3);
                    if (sg > tt) acc_s[ni][q] = -1e30f;
                }
            }
        }

        float mx0 = -1e30f, mx1 = -1e30f;
#pragma unroll
        for (int ni = 0; ni < 8; ni++) {
            mx0 = fmaxf(mx0, fmaxf(acc_s[ni][0], acc_s[ni][1]));
            mx1 = fmaxf(mx1, fmaxf(acc_s[ni][2], acc_s[ni][3]));
        }
        mx0 = fmaxf(mx0, __shfl_xor_sync(0xffffffffu, mx0, 1));
        mx0 = fmaxf(mx0, __shfl_xor_sync(0xffffffffu, mx0, 2));
        mx1 = fmaxf(mx1, __shfl_xor_sync(0xffffffffu, mx1, 1));
        mx1 = fmaxf(mx1, __shfl_xor_sync(0xffffffffu, mx1, 2));
        float nm0 = fmaxf(m0r, mx0), nm1 = fmaxf(m1r, mx1);
        float sc0 = __expf(m0r - nm0), sc1 = __expf(m1r - nm1);
        m0r = nm0; m1r = nm1;

        float sum0 = 0.f, sum1 = 0.f;
#pragma unroll
        for (int ni = 0; ni < 8; ni++) {
            acc_s[ni][0] = __expf(acc_s[ni][0] - m0r);
            acc_s[ni][1] = __expf(acc_s[ni][1] - m0r);
            acc_s[ni][2] = __expf(acc_s[ni][2] - m1r);
            acc_s[ni][3] = __expf(acc_s[ni][3] - m1r);
            sum0 += acc_s[ni][0] + acc_s[ni][1];
            sum1 += acc_s[ni][2] + acc_s[ni][3];
        }
        sum0 += __shfl_xor_sync(0xffffffffu, sum0, 1);
        sum0 += __shfl_xor_sync(0xffffffffu, sum0, 2);
        sum1 += __shfl_xor_sync(0xffffffffu, sum1, 1);
        sum1 += __shfl_xor_sync(0xffffffffu, sum1, 2);
        l0r = l0r * sc0 + sum0;
        l1r = l1r * sc1 + sum1;

#pragma unroll
        for (int nd = 0; nd < 16; nd++) {
            acc_o[nd][0] *= sc0; acc_o[nd][1] *= sc0;
            acc_o[nd][2] *= sc1; acc_o[nd][3] *= sc1;
        }

        uint32_t pf[4][4];
#pragma unroll
        for (int kk = 0; kk < 4; kk++) {
            pf[kk][0] = pack2h(acc_s[2 * kk][0],     acc_s[2 * kk][1]);
            pf[kk][1] = pack2h(acc_s[2 * kk][2],     acc_s[2 * kk][3]);
            pf[kk][2] = pack2h(acc_s[2 * kk + 1][0], acc_s[2 * kk + 1][1]);
            pf[kk][3] = pack2h(acc_s[2 * kk + 1][2], acc_s[2 * kk + 1][3]);
        }

#pragma unroll
        for (int kk = 0; kk < 4; kk++) {
#pragma unroll
            for (int nd = 0; nd < 16; nd++) {
                uint32_t b_f[2];
                ldm_x2_trans(vb_ + (kk * 16) * FA_LDK + v_off + nd * 16, b_f);
                mma_f16(acc_o[nd], pf[kk], b_f);
            }
        }
        __syncthreads();
    }

    const float inv0 = 1.f / l0r, inv1 = 1.f / l1r;
    const int b = bh >> 4, h = bh & (Hh - 1);
#pragma unroll
    for (int nd = 0; nd < 16; nd++) {
        int d = nd * 8 + tc * 2;
        size_t i0 = (((size_t)(b * Tt + t0) * Hh) + h) * DK + d;
        size_t i1 = (((size_t)(b * Tt + t0 + 8) * Hh) + h) * DK + d;
        *reinterpret_cast<__half2*>(g_ah + i0) =
            __halves2half2(__float2half(acc_o[nd][0] * inv0),
                           __float2half(acc_o[nd][1] * inv0));
        *reinterpret_cast<__half2*>(g_ah + i1) =
            __halves2half2(__float2half(acc_o[nd][2] * inv1),
                           __float2half(acc_o[nd][3] * inv1));
    }
}

// ---------------------------------------------------------------------------
extern "C" void kernel_launch(void* const* d_in, const int* in_sizes, int n_in,
                              void* d_out, int out_size) {
    const float* x  = (const float*)d_in[0];
    const float* ck = (const float*)d_in[1];
    const float* cv = (const float*)d_in[2];
    const float* Wq = (const float*)d_in[3];
    const float* Wk = (const float*)d_in[4];
    const float* Wv = (const float*)d_in[5];
    const float* Wo = (const float*)d_in[6];

    float* out  = (float*)d_out;
    float* Kout = out + (size_t)Bb * Tt * Cc;
    float* Vout = Kout + (size_t)Bb * Hh * SS * DK;

    static cudaStream_t s1 = nullptr;
    static cudaEvent_t evFork = nullptr, evKV = nullptr, evXW = nullptr, evKV2 = nullptr;
    if (s1 == nullptr) {
        cudaStreamCreateWithFlags(&s1, cudaStreamNonBlocking);
        cudaEventCreateWithFlags(&evFork, cudaEventDisableTiming);
        cudaEventCreateWithFlags(&evKV,   cudaEventDisableTiming);
        cudaEventCreateWithFlags(&evXW,   cudaEventDisableTiming);
        cudaEventCreateWithFlags(&evKV2,  cudaEventDisableTiming);
        cudaFuncSetAttribute(mm_hmma_kernel, cudaFuncAttributeMaxDynamicSharedMemorySize, MM_SMEM);
        cudaFuncSetAttribute(fa_kernel, cudaFuncAttributeMaxDynamicSharedMemorySize, FA_SMEM);
    }

    // fork
    cudaEventRecord(evFork, 0);
    cudaStreamWaitEvent(s1, evFork, 0);

    // s1: cache convert/copy, then (after conv_xw) the K/V projections
    convert_kv_kernel<<<8192, 256, 0, s1>>>((const float4*)ck, (const float4*)cv,
                                            (float4*)Kout, (float4*)Vout);
    cudaEventRecord(evKV, s1);

    // main: x/W convert -> Q projection
    convert_xw_kernel<<<20480, 256>>>((const float4*)x, (const float4*)Wq,
                                      (const float4*)Wk, (const float4*)Wv,
                                      (const float4*)Wo);
    cudaEventRecord(evXW, 0);

    // s1: K/V new-token projections (overlap with fa + mm1 on main)
    cudaStreamWaitEvent(s1, evXW, 0);
    mm_hmma_kernel<<<dim3(16, 16, 2), 256, MM_SMEM, s1>>>(0, 1, Kout, Vout, out);
    cudaEventRecord(evKV2, s1);

    // main: Q projection -> flash attention -> output projection
    mm_hmma_kernel<<<dim3(16, 16, 1), 256, MM_SMEM>>>(0, 0, Kout, Vout, out);
    cudaStreamWaitEvent(0, evKV, 0);
    fa_kernel<<<dim3(8, 32), 256, FA_SMEM>>>();
    mm_hmma_kernel<<<dim3(16, 16, 1), 256, MM_SMEM>>>(1, 0, Kout, Vout, out);

    // join
    cudaStreamWaitEvent(0, evKV2, 0);
}

// round 17
// speedup vs baseline: 1.1677x; 1.0002x over previous
#include <cuda_runtime.h>
#include <cuda_fp16.h>
#include <math.h>
#include <stdint.h>

// Problem dims
#define Bb 2
#define Tt 1024
#define Cc 2048
#define Hh 16
#define DK 128
#define SC 1024
#define SS 2048
#define KDIM 2048
#define NMAT 4194304ull   // 2048*2048

#define RSQRT_DK 0.08838834764831845f

// HMMA GEMM tiling: CTA tile 128(M) x 128(N) x 64(K), 256 threads,
// 8 warps 2(m) x 4(n), warp tile 64x32. 2-stage pipeline, BK=64.
#define MM_BK 64
#define MM_LDS_B 144                       // bytes per smem row (64 fp16 + 16 pad)
#define MM_MATA 18432                      // 128 rows * 144
#define MM_STAGE (2 * MM_MATA)             // 36864 (A + B)
#define MM_SMEM (2 * MM_STAGE)             // 73728
#define MM_KSTEPS (KDIM / MM_BK)           // 32

// Flash-attention tiling: m-tile 128, s-tile 64, d=128, 8 warps (16 rows each)
#define FA_LDQ 272
#define FA_LDK 272
#define FA_QBYTES (128 * FA_LDQ)           // 34816
#define FA_KBYTES (64 * FA_LDK)            // 17408
#define FA_KV_STAGE (2 * FA_KBYTES)        // 34816
#define FA_SMEM (FA_QBYTES + 2 * FA_KV_STAGE)  // 104448

// ---------------------------------------------------------------------------
// Scratch (device globals)
// ---------------------------------------------------------------------------
__device__ __half g_xh[NMAT];                             // x fp16
__device__ __half g_w4[4 * NMAT];                         // Wq,Wk,Wv,Wo fp16
__device__ __half g_kc[NMAT];                             // cache_k fp16
__device__ __half g_vc[NMAT];                             // cache_v fp16
__device__ __half g_qh[NMAT];                             // Q fp16 [bh,t,d] scaled
__device__ __half g_ah[NMAT];                             // attn fp16 [b,t,h,d]

// ---------------------------------------------------------------------------
// PTX helpers
// ---------------------------------------------------------------------------
__device__ __forceinline__ uint32_t smem_u32(const void* p) {
    uint32_t a;
    asm("{ .reg .u64 t; cvta.to.shared.u64 t, %1; cvt.u32.u64 %0, t; }" : "=r"(a) : "l"(p));
    return a;
}
#define CP_ASYNC16(saddr, gaddr) \
    asm volatile("cp.async.cg.shared.global [%0], [%1], 16;" :: "r"(saddr), "l"(gaddr))
#define CP_COMMIT() asm volatile("cp.async.commit_group;" ::: "memory")
#define CP_WAIT(n)  asm volatile("cp.async.wait_group %0;" :: "n"(n) : "memory")

__device__ __forceinline__ void ldm_x4(uint32_t addr, uint32_t* r) {
    asm volatile("ldmatrix.sync.aligned.m8n8.x4.shared.b16 {%0,%1,%2,%3}, [%4];"
        : "=r"(r[0]), "=r"(r[1]), "=r"(r[2]), "=r"(r[3]) : "r"(addr));
}
__device__ __forceinline__ void ldm_x4_trans(uint32_t addr, uint32_t* r) {
    asm volatile("ldmatrix.sync.aligned.m8n8.x4.trans.shared.b16 {%0,%1,%2,%3}, [%4];"
        : "=r"(r[0]), "=r"(r[1]), "=r"(r[2]), "=r"(r[3]) : "r"(addr));
}
__device__ __forceinline__ void mma_f16(float* d, const uint32_t* a, const uint32_t* b) {
    asm volatile("mma.sync.aligned.m16n8k16.row.col.f32.f16.f16.f32 "
        "{%0,%1,%2,%3}, {%4,%5,%6,%7}, {%8,%9}, {%0,%1,%2,%3};"
        : "+f"(d[0]), "+f"(d[1]), "+f"(d[2]), "+f"(d[3])
        : "r"(a[0]), "r"(a[1]), "r"(a[2]), "r"(a[3]), "r"(b[0]), "r"(b[1]));
}
__device__ __forceinline__ uint32_t pack2h(float a, float b) {
    __half2 h = __floats2half2_rn(a, b);
    return *reinterpret_cast<uint32_t*>(&h);
}

// ---------------------------------------------------------------------------
// convert_xw: x -> fp16 (g_xh), Wq/Wk/Wv/Wo -> fp16 (g_w4). 5 matrices.
// ---------------------------------------------------------------------------
__global__ void convert_xw_kernel(const float4* __restrict__ x,
                                  const float4* __restrict__ wq,
                                  const float4* __restrict__ wk,
                                  const float4* __restrict__ wv,
                                  const float4* __restrict__ wo) {
    int id = blockIdx.x * blockDim.x + threadIdx.x;
    const int per = (int)(NMAT / 4);
    int mat = id / per;
    int rem = id - mat * per;
    const float4* srcs[5] = {x, wq, wk, wv, wo};
    float4 v = srcs[mat][rem];
    __half* base = (mat == 0) ? g_xh : (g_w4 + (size_t)(mat - 1) * NMAT);
    __half2* d = reinterpret_cast<__half2*>(base) + rem * 2;
    d[0] = __halves2half2(__float2half(v.x), __float2half(v.y));
    d[1] = __halves2half2(__float2half(v.z), __float2half(v.w));
}

// ---------------------------------------------------------------------------
// convert_kv: ck/cv -> fp16 AND fp32 copy into output K/V slots (forked stream)
// ---------------------------------------------------------------------------
__global__ void convert_kv_kernel(const float4* __restrict__ ck,
                                  const float4* __restrict__ cv,
                                  float4* __restrict__ Kout,
                                  float4* __restrict__ Vout) {
    int id = blockIdx.x * blockDim.x + threadIdx.x;
    const int per = (int)(NMAT / 4);
    int mat = id / per;              // 0 = K, 1 = V
    int rem = id - mat * per;
    float4 v = (mat ? cv : ck)[rem];
    __half* base = mat ? g_vc : g_kc;
    __half2* d = reinterpret_cast<__half2*>(base) + rem * 2;
    d[0] = __halves2half2(__float2half(v.x), __float2half(v.y));
    d[1] = __halves2half2(__float2half(v.z), __float2half(v.w));
    int pos = rem & 31;
    int row = rem >> 5;
    int s = row & (SC - 1);
    int bh = row >> 10;
    int dst = (((bh * SS) + s) << 5) + pos;
    (mat ? Vout : Kout)[dst] = v;
}

// ---------------------------------------------------------------------------
// HMMA fp16 GEMM (256 threads, 8 warps 2x4, CTA 128x128, BK=64, 2-stage)
// mode 0: A=x, B=W[pbase+blockIdx.z]; proj0 -> Q fp16, proj1/2 -> K/V fp32
// mode 1: A=attn, B=Wo; -> out fp32
// ---------------------------------------------------------------------------
__global__ __launch_bounds__(256, 2)
void mm_hmma_kernel(int mode, int pbase, float* __restrict__ Kout,
                    float* __restrict__ Vout, float* __restrict__ out) {
    extern __shared__ char sm[];
    const uint32_t sbu = smem_u32(sm);
    const int tid = threadIdx.x;
    const int wid = tid >> 5, lane = tid & 31;
    const int warp_m = wid >> 2;          // 0..1
    const int warp_n = wid & 3;           // 0..3

    const int proj = pbase + blockIdx.z;
    const __half *As, *Bs;
    if (mode == 0) {
        As = g_xh;
        Bs = g_w4 + (size_t)proj * NMAT;
    } else {
        As = g_ah;
        Bs = g_w4 + (size_t)3 * NMAT;
    }
    const int m0 = blockIdx.x * 128, n0 = blockIdx.y * 128;

    const __half* gptr[8];
    uint32_t soff[8];
#pragma unroll
    for (int j = 0; j < 8; j++) {
        int c = j * 256 + tid;
        int idx = c & 1023;
        int r = idx >> 3, c8 = idx & 7;
        if (c < 1024) {
            gptr[j] = As + (size_t)(m0 + r) * KDIM + c8 * 8;
            soff[j] = (uint32_t)(r * MM_LDS_B + c8 * 16);
        } else {
            gptr[j] = Bs + (size_t)(n0 + r) * KDIM + c8 * 8;
            soff[j] = (uint32_t)(MM_MATA + r * MM_LDS_B + c8 * 16);
        }
    }

    const uint32_t a_row  = (uint32_t)(warp_m * 64 + (lane & 15));
    const uint32_t a_kb   = (uint32_t)(((lane >> 4) << 3) * 2);
    const uint32_t b_row4 = (uint32_t)(warp_n * 32 + (lane & 7) + ((lane >> 4) << 3));
    const uint32_t b_kb4  = (uint32_t)(((lane >> 3) & 1) << 4);

    float acc[4][4][4];
#pragma unroll
    for (int mi = 0; mi < 4; mi++)
#pragma unroll
        for (int ni = 0; ni < 4; ni++)
#pragma unroll
            for (int q = 0; q < 4; q++) acc[mi][ni][q] = 0.f;

#pragma unroll
    for (int j = 0; j < 8; j++) CP_ASYNC16(sbu + soff[j], gptr[j]);
    CP_COMMIT();

    for (int i = 0; i < MM_KSTEPS; i++) {
        __syncthreads();
        if (i + 1 < MM_KSTEPS) {
            const uint32_t sb2 = sbu + ((i + 1) & 1) * MM_STAGE;
            const int k0 = (i + 1) * MM_BK;
#pragma unroll
            for (int j = 0; j < 8; j++) CP_ASYNC16(sb2 + soff[j], gptr[j] + k0);
            CP_COMMIT();
            CP_WAIT(1);
        } else {
            CP_WAIT(0);
        }
        __syncthreads();

        const uint32_t stage = sbu + (i & 1) * MM_STAGE;
#pragma unroll
        for (int kk = 0; kk < 4; kk++) {
            const uint32_t kb = (uint32_t)(kk * 32);
            uint32_t a_f[4][4], b4[2][4];
#pragma unroll
            for (int nj = 0; nj < 2; nj++) {
                uint32_t baddr = stage + MM_MATA +
                                 (b_row4 + nj * 16) * MM_LDS_B + b_kb4 + kb;
                ldm_x4(baddr, b4[nj]);
            }
#pragma unroll
            for (int mi = 0; mi < 4; mi++) {
                uint32_t aaddr = stage + (a_row + mi * 16) * MM_LDS_B + a_kb + kb;
                ldm_x4(aaddr, a_f[mi]);
            }
#pragma unroll
            for (int mi = 0; mi < 4; mi++)
#pragma unroll
                for (int ni = 0; ni < 4; ni++)
                    mma_f16(acc[mi][ni], a_f[mi], &b4[ni >> 1][(ni & 1) * 2]);
        }
    }

    const int gid = lane >> 2, tc = lane & 3;
#pragma unroll
    for (int mi = 0; mi < 4; mi++) {
#pragma unroll
        for (int ni = 0; ni < 4; ni++) {
            int mrow0 = m0 + warp_m * 64 + mi * 16 + gid;
            int ncol  = n0 + warp_n * 32 + ni * 8 + tc * 2;
#pragma unroll
            for (int half = 0; half < 2; half++) {
                int m = mrow0 + half * 8;
                float v0 = acc[mi][ni][half * 2 + 0];
                float v1 = acc[mi][ni][half * 2 + 1];
                if (mode == 0) {
                    int b = m >> 10, t = m & (Tt - 1);
                    int h = ncol >> 7, d = ncol & (DK - 1);
                    if (proj == 0) {
                        size_t qi = (((size_t)(b * Hh + h) * Tt) + t) * DK + d;
                        *reinterpret_cast<__half2*>(g_qh + qi) =
                            __halves2half2(__float2half(v0 * RSQRT_DK),
                                           __float2half(v1 * RSQRT_DK));
                    } else {
                        float* base = (proj == 1) ? Kout : Vout;
                        float* dst = base + (((size_t)(b * Hh + h) * SS) + SC + t) * DK + d;
                        float2 vv; vv.x = v0; vv.y = v1;
                        *reinterpret_cast<float2*>(dst) = vv;
                    }
                } else {
                    float* dst = out + (size_t)m * Cc + ncol;
                    float2 vv; vv.x = v0; vv.y = v1;
                    *reinterpret_cast<float2*>(dst) = vv;
                }
            }
        }
    }
}

// ---------------------------------------------------------------------------
// Fused flash attention (occupancy 1). x4 ldmatrix for K and V fragments.
// ---------------------------------------------------------------------------
__global__ __launch_bounds__(256, 1)
void fa_kernel() {
    extern __shared__ char sm[];
    const uint32_t sbu = smem_u32(sm);
    const int tid = threadIdx.x;
    const int wid = tid >> 5, lane = tid & 31;
    const int gid = lane >> 2, tc = lane & 3;

    const int mt = 7 - blockIdx.x;
    const int bh = blockIdx.y;
    const int m0 = mt * 128;
    const int nst = (mt + 1) * 2;

    const __half* Qg = g_qh + (size_t)bh * Tt * DK + (size_t)m0 * DK;
    const __half* Kg = g_kc + (size_t)bh * SC * DK;
    const __half* Vg = g_vc + (size_t)bh * SC * DK;

    const uint32_t qs  = sbu;
    const uint32_t kvs = sbu + FA_QBYTES;

#pragma unroll
    for (int j = 0; j < 8; j++) {
        int c = j * 256 + tid;
        int row = c >> 4, col = c & 15;
        CP_ASYNC16(qs + row * FA_LDQ + col * 16, Qg + (size_t)row * DK + col * 8);
    }
    const __half* kvg[8];
    uint32_t kvo[8];
#pragma unroll
    for (int j = 0; j < 8; j++) {
        int c = j * 256 + tid;
        int mat = c >> 10;
        int idx = c & 1023;
        int row = idx >> 4, col = idx & 15;
        kvg[j] = (mat ? Vg : Kg) + (size_t)row * DK + col * 8;
        kvo[j] = (uint32_t)(mat * FA_KBYTES + row * FA_LDK + col * 16);
    }
#pragma unroll
    for (int j = 0; j < 8; j++) CP_ASYNC16(kvs + kvo[j], kvg[j]);
    CP_COMMIT();

    float acc_o[16][4];
#pragma unroll
    for (int nd = 0; nd < 16; nd++)
#pragma unroll
        for (int q = 0; q < 4; q++) acc_o[nd][q] = 0.f;

    float m0r = -1e30f, m1r = -1e30f, l0r = 0.f, l1r = 0.f;
    const int t0 = m0 + wid * 16 + gid;

    const uint32_t a_off  = (uint32_t)((wid * 16 + (lane & 15)) * FA_LDQ + ((lane >> 4) << 4));
    // x4 K fragments: lanes 0-15 -> ni tile (rows lane&7, k halves), lanes 16-31 -> ni+1 tile
    const uint32_t b_off4 = (uint32_t)(((lane & 7) + ((lane >> 4) << 3)) * FA_LDK +
                                       (((lane >> 3) & 1) << 4));
    // x4 trans V fragments: lanes 0-15 -> nd tile (16 k-rows), lanes 16-31 -> nd+1 tile
    const uint32_t v_off4 = (uint32_t)((lane & 15) * FA_LDK + ((lane >> 4) << 4));

    for (int i = 0; i < nst; i++) {
        const int s = i & 1;
        if (i + 1 < nst) {
            const uint32_t kv2 = kvs + ((i + 1) & 1) * FA_KV_STAGE;
            const size_t off = (size_t)(i + 1) * 64 * DK;
#pragma unroll
            for (int j = 0; j < 8; j++) CP_ASYNC16(kv2 + kvo[j], kvg[j] + off);
            CP_COMMIT();
            CP_WAIT(1);
        } else {
            CP_WAIT(0);
        }
        __syncthreads();

        const uint32_t kb_ = kvs + s * FA_KV_STAGE;
        const uint32_t vb_ = kb_ + FA_KBYTES;

        // --- S = Q . K^T ---
        float acc_s[8][4];
#pragma unroll
        for (int ni = 0; ni < 8; ni++)
#pragma unroll
            for (int q = 0; q < 4; q++) acc_s[ni][q] = 0.f;
#pragma unroll
        for (int kk = 0; kk < 8; kk++) {
            uint32_t a_f[4];
            ldm_x4(qs + a_off + kk * 32, a_f);
#pragma unroll
            for (int nj = 0; nj < 4; nj++) {
                uint32_t bf4[4];
                ldm_x4(kb_ + b_off4 + nj * 16 * FA_LDK + kk * 32, bf4);
                mma_f16(acc_s[2 * nj + 0], a_f, bf4 + 0);
                mma_f16(acc_s[2 * nj + 1], a_f, bf4 + 2);
            }
        }

        // --- causal mask ---
        if (i >= nst - 2) {
            const int sbase = i * 64;
#pragma unroll
            for (int ni = 0; ni < 8; ni++) {
#pragma unroll
                for (int q = 0; q < 4; q++) {
                    int sg = sbase + ni * 8 + tc * 2 + (q & 1);
                    int tt = t0 + ((q >> 1) << 3);
                    if (sg > tt) acc_s[ni][q] = -1e30f;
                }
            }
        }

        // --- online softmax ---
        float mx0 = -1e30f, mx1 = -1e30f;
#pragma unroll
        for (int ni = 0; ni < 8; ni++) {
            mx0 = fmaxf(mx0, fmaxf(acc_s[ni][0], acc_s[ni][1]));
            mx1 = fmaxf(mx1, fmaxf(acc_s[ni][2], acc_s[ni][3]));
        }
        mx0 = fmaxf(mx0, __shfl_xor_sync(0xffffffffu, mx0, 1));
        mx0 = fmaxf(mx0, __shfl_xor_sync(0xffffffffu, mx0, 2));
        mx1 = fmaxf(mx1, __shfl_xor_sync(0xffffffffu, mx1, 1));
        mx1 = fmaxf(mx1, __shfl_xor_sync(0xffffffffu, mx1, 2));
        float nm0 = fmaxf(m0r, mx0), nm1 = fmaxf(m1r, mx1);
        float sc0 = __expf(m0r - nm0), sc1 = __expf(m1r - nm1);
        m0r = nm0; m1r = nm1;

        float sum0 = 0.f, sum1 = 0.f;
#pragma unroll
        for (int ni = 0; ni < 8; ni++) {
            acc_s[ni][0] = __expf(acc_s[ni][0] - m0r);
            acc_s[ni][1] = __expf(acc_s[ni][1] - m0r);
            acc_s[ni][2] = __expf(acc_s[ni][2] - m1r);
            acc_s[ni][3] = __expf(acc_s[ni][3] - m1r);
            sum0 += acc_s[ni][0] + acc_s[ni][1];
            sum1 += acc_s[ni][2] + acc_s[ni][3];
        }
        sum0 += __shfl_xor_sync(0xffffffffu, sum0, 1);
        sum0 += __shfl_xor_sync(0xffffffffu, sum0, 2);
        sum1 += __shfl_xor_sync(0xffffffffu, sum1, 1);
        sum1 += __shfl_xor_sync(0xffffffffu, sum1, 2);
        l0r = l0r * sc0 + sum0;
        l1r = l1r * sc1 + sum1;

#pragma unroll
        for (int nd = 0; nd < 16; nd++) {
            acc_o[nd][0] *= sc0; acc_o[nd][1] *= sc0;
            acc_o[nd][2] *= sc1; acc_o[nd][3] *= sc1;
        }

        uint32_t pf[4][4];
#pragma unroll
        for (int kk = 0; kk < 4; kk++) {
            pf[kk][0] = pack2h(acc_s[2 * kk][0],     acc_s[2 * kk][1]);
            pf[kk][1] = pack2h(acc_s[2 * kk][2],     acc_s[2 * kk][3]);
            pf[kk][2] = pack2h(acc_s[2 * kk + 1][0], acc_s[2 * kk + 1][1]);
            pf[kk][3] = pack2h(acc_s[2 * kk + 1][2], acc_s[2 * kk + 1][3]);
        }

        // --- O += P . V (x4 trans: 2 nd tiles per ldmatrix) ---
#pragma unroll
        for (int kk = 0; kk < 4; kk++) {
#pragma unroll
            for (int ndp = 0; ndp < 8; ndp++) {
                uint32_t bf4[4];
                ldm_x4_trans(vb_ + (kk * 16) * FA_LDK + v_off4 + ndp * 32, bf4);
                mma_f16(acc_o[2 * ndp + 0], pf[kk], bf4 + 0);
                mma_f16(acc_o[2 * ndp + 1], pf[kk], bf4 + 2);
            }
        }
        __syncthreads();
    }

    const float inv0 = 1.f / l0r, inv1 = 1.f / l1r;
    const int b = bh >> 4, h = bh & (Hh - 1);
#pragma unroll
    for (int nd = 0; nd < 16; nd++) {
        int d = nd * 8 + tc * 2;
        size_t i0 = (((size_t)(b * Tt + t0) * Hh) + h) * DK + d;
        size_t i1 = (((size_t)(b * Tt + t0 + 8) * Hh) + h) * DK + d;
        *reinterpret_cast<__half2*>(g_ah + i0) =
            __halves2half2(__float2half(acc_o[nd][0] * inv0),
                           __float2half(acc_o[nd][1] * inv0));
        *reinterpret_cast<__half2*>(g_ah + i1) =
            __halves2half2(__float2half(acc_o[nd][2] * inv1),
                           __float2half(acc_o[nd][3] * inv1));
    }
}

// ---------------------------------------------------------------------------
extern "C" void kernel_launch(void* const* d_in, const int* in_sizes, int n_in,
                              void* d_out, int out_size) {
    const float* x  = (const float*)d_in[0];
    const float* ck = (const float*)d_in[1];
    const float* cv = (const float*)d_in[2];
    const float* Wq = (const float*)d_in[3];
    const float* Wk = (const float*)d_in[4];
    const float* Wv = (const float*)d_in[5];
    const float* Wo = (const float*)d_in[6];

    float* out  = (float*)d_out;
    float* Kout = out + (size_t)Bb * Tt * Cc;
    float* Vout = Kout + (size_t)Bb * Hh * SS * DK;

    static cudaStream_t s1 = nullptr;
    static cudaEvent_t evFork = nullptr, evKV = nullptr, evXW = nullptr, evKV2 = nullptr;
    if (s1 == nullptr) {
        cudaStreamCreateWithFlags(&s1, cudaStreamNonBlocking);
        cudaEventCreateWithFlags(&evFork, cudaEventDisableTiming);
        cudaEventCreateWithFlags(&evKV,   cudaEventDisableTiming);
        cudaEventCreateWithFlags(&evXW,   cudaEventDisableTiming);
        cudaEventCreateWithFlags(&evKV2,  cudaEventDisableTiming);
        cudaFuncSetAttribute(mm_hmma_kernel, cudaFuncAttributeMaxDynamicSharedMemorySize, MM_SMEM);
        cudaFuncSetAttribute(fa_kernel, cudaFuncAttributeMaxDynamicSharedMemorySize, FA_SMEM);
    }

    // fork
    cudaEventRecord(evFork, 0);
    cudaStreamWaitEvent(s1, evFork, 0);

    // s1: cache convert/copy, then (after conv_xw) the K/V projections
    convert_kv_kernel<<<8192, 256, 0, s1>>>((const float4*)ck, (const float4*)cv,
                                            (float4*)Kout, (float4*)Vout);
    cudaEventRecord(evKV, s1);

    // main: x/W convert -> Q projection
    convert_xw_kernel<<<20480, 256>>>((const float4*)x, (const float4*)Wq,
                                      (const float4*)Wk, (const float4*)Wv,
                                      (const float4*)Wo);
    cudaEventRecord(evXW, 0);

    // s1: K/V new-token projections (overlap with fa + mm1 on main)
    cudaStreamWaitEvent(s1, evXW, 0);
    mm_hmma_kernel<<<dim3(16, 16, 2), 256, MM_SMEM, s1>>>(0, 1, Kout, Vout, out);
    cudaEventRecord(evKV2, s1);

    // main: Q projection -> flash attention -> output projection
    mm_hmma_kernel<<<dim3(16, 16, 1), 256, MM_SMEM>>>(0, 0, Kout, Vout, out);
    cudaStreamWaitEvent(0, evKV, 0);
    fa_kernel<<<dim3(8, 32), 256, FA_SMEM>>>();
    mm_hmma_kernel<<<dim3(16, 16, 1), 256, MM_SMEM>>>(1, 0, Kout, Vout, out);

    // join
    cudaStreamWaitEvent(0, evKV2, 0);
}